// round 1
// baseline (speedup 1.0000x reference)
#include <cuda_runtime.h>
#include <cuda_fp16.h>
#include <cstdint>

// Problem dims: B=32, L=1024, E=512, D=512.  M = B*L = 32768 rows, N = 8D = 4096.
// Layer0: K=512, Layer1: K=1024.

#define M_ROWS 32768
#define N_COLS 4096
#define SCALE_F 1.4142135623730951f

// ---------------------------------------------------------------------------
// Scratch (device globals — no allocations allowed)
// ---------------------------------------------------------------------------
__device__ __half g_Ah[33554432];   // fp16 A: layer0 seqs (32768x512), then h0 (32768x1024)
__device__ __half g_Wh[4194304];    // fp16 W (K x 4096), reused per layer
__device__ float  g_U[134217728];   // fp32 U (32768 x 4096), reused per layer

// ---------------------------------------------------------------------------
// fp32 -> fp16 converters
// ---------------------------------------------------------------------------
__global__ void k_cvtA(const float4* __restrict__ s, int n4) {
    int i = blockIdx.x * blockDim.x + threadIdx.x;
    if (i < n4) {
        float4 v = s[i];
        __half2* dp = reinterpret_cast<__half2*>(g_Ah);
        dp[2 * i]     = __floats2half2_rn(v.x, v.y);
        dp[2 * i + 1] = __floats2half2_rn(v.z, v.w);
    }
}

__global__ void k_cvtW(const float4* __restrict__ s, int n4) {
    int i = blockIdx.x * blockDim.x + threadIdx.x;
    if (i < n4) {
        float4 v = s[i];
        __half2* dp = reinterpret_cast<__half2*>(g_Wh);
        dp[2 * i]     = __floats2half2_rn(v.x, v.y);
        dp[2 * i + 1] = __floats2half2_rn(v.z, v.w);
    }
}

// ---------------------------------------------------------------------------
// fp16 GEMM: C(fp32, MxN) = A(fp16, MxK) * W(fp16, KxN)
// Tiles: BM=128 BN=128 BK=32, 256 threads (8 warps, 2x4), warp tile 64x32.
// mma.sync.m16n8k16, cp.async double buffered smem.
// ---------------------------------------------------------------------------
#define BM 128
#define BN 128
#define BK 32
#define PADA 8   // halves -> row stride 80B (16B-aligned, conflict-free ldmatrix)
#define PADB 8   // halves -> row stride 272B

__device__ __forceinline__ void mma16816(float c[4], const uint32_t a[4], const uint32_t b[2]) {
    asm volatile(
        "mma.sync.aligned.m16n8k16.row.col.f32.f16.f16.f32 "
        "{%0,%1,%2,%3}, {%4,%5,%6,%7}, {%8,%9}, {%0,%1,%2,%3};\n"
        : "+f"(c[0]), "+f"(c[1]), "+f"(c[2]), "+f"(c[3])
        : "r"(a[0]), "r"(a[1]), "r"(a[2]), "r"(a[3]), "r"(b[0]), "r"(b[1]));
}

template <int K>
__global__ __launch_bounds__(256) void k_gemm() {
    __shared__ __align__(16) __half As[2][BM][BK + PADA];
    __shared__ __align__(16) __half Bs[2][BK][BN + PADB];

    const int tid  = threadIdx.x;
    const int warp = tid >> 5;
    const int lane = tid & 31;
    const int wm = warp & 1;   // 0..1 -> 64-row slab
    const int wn = warp >> 1;  // 0..3 -> 32-col slab
    const size_t rowBase = (size_t)blockIdx.y * BM;
    const int    colBase = blockIdx.x * BN;

    const __half* Ag = g_Ah;
    const __half* Wg = g_Wh;

    float acc[4][4][4];
#pragma unroll
    for (int i = 0; i < 4; i++)
#pragma unroll
        for (int j = 0; j < 4; j++)
#pragma unroll
            for (int k = 0; k < 4; k++) acc[i][j][k] = 0.0f;

    auto loadStage = [&](int kt, int buf) {
#pragma unroll
        for (int i = 0; i < 2; i++) {   // A: 512 16B-chunks / 256 threads
            int cid = tid + i * 256;
            int r = cid >> 2, ch = cid & 3;
            const __half* g = Ag + (rowBase + r) * (size_t)K + kt * BK + ch * 8;
            uint32_t s = (uint32_t)__cvta_generic_to_shared(&As[buf][r][ch * 8]);
            asm volatile("cp.async.cg.shared.global [%0], [%1], 16;\n" :: "r"(s), "l"(g));
        }
#pragma unroll
        for (int i = 0; i < 2; i++) {   // B: 512 16B-chunks / 256 threads
            int cid = tid + i * 256;
            int r = cid >> 4, ch = cid & 15;
            const __half* g = Wg + (size_t)(kt * BK + r) * N_COLS + colBase + ch * 8;
            uint32_t s = (uint32_t)__cvta_generic_to_shared(&Bs[buf][r][ch * 8]);
            asm volatile("cp.async.cg.shared.global [%0], [%1], 16;\n" :: "r"(s), "l"(g));
        }
        asm volatile("cp.async.commit_group;\n" ::: "memory");
    };

    loadStage(0, 0);
    const int KT = K / BK;
    int buf = 0;
    for (int kt = 0; kt < KT; kt++) {
        asm volatile("cp.async.wait_group 0;\n" ::: "memory");
        __syncthreads();
        if (kt + 1 < KT) loadStage(kt + 1, buf ^ 1);

#pragma unroll
        for (int kk = 0; kk < 2; kk++) {  // two k16 halves of BK=32
            uint32_t a[4][4];
#pragma unroll
            for (int mt = 0; mt < 4; mt++) {
                int row = wm * 64 + mt * 16 + (lane & 15);
                int col = kk * 16 + (lane >> 4) * 8;
                uint32_t s = (uint32_t)__cvta_generic_to_shared(&As[buf][row][col]);
                asm volatile("ldmatrix.sync.aligned.m8n8.x4.shared.b16 {%0,%1,%2,%3}, [%4];\n"
                             : "=r"(a[mt][0]), "=r"(a[mt][1]), "=r"(a[mt][2]), "=r"(a[mt][3])
                             : "r"(s));
            }
            uint32_t bf[4][2];
#pragma unroll
            for (int nh = 0; nh < 2; nh++) {  // each x4.trans feeds two n8 tiles
                int krow = kk * 16 + (lane & 15);
                int ncol = wn * 32 + nh * 16 + (lane >> 4) * 8;
                uint32_t s = (uint32_t)__cvta_generic_to_shared(&Bs[buf][krow][ncol]);
                uint32_t r0, r1, r2, r3;
                asm volatile("ldmatrix.sync.aligned.m8n8.x4.trans.shared.b16 {%0,%1,%2,%3}, [%4];\n"
                             : "=r"(r0), "=r"(r1), "=r"(r2), "=r"(r3)
                             : "r"(s));
                bf[nh * 2][0] = r0; bf[nh * 2][1] = r1;
                bf[nh * 2 + 1][0] = r2; bf[nh * 2 + 1][1] = r3;
            }
#pragma unroll
            for (int mt = 0; mt < 4; mt++)
#pragma unroll
                for (int nt = 0; nt < 4; nt++)
                    mma16816(acc[mt][nt], a[mt], bf[nt]);
        }
        buf ^= 1;
    }

    // Epilogue -> g_U fp32
#pragma unroll
    for (int mt = 0; mt < 4; mt++) {
#pragma unroll
        for (int nt = 0; nt < 4; nt++) {
            int r0 = wm * 64 + mt * 16 + (lane >> 2);
            int c0 = wn * 32 + nt * 8 + (lane & 3) * 2;
            float* o1 = g_U + (rowBase + r0) * (size_t)N_COLS + colBase + c0;
            float* o2 = g_U + (rowBase + r0 + 8) * (size_t)N_COLS + colBase + c0;
            *reinterpret_cast<float2*>(o1) = make_float2(acc[mt][nt][0], acc[mt][nt][1]);
            *reinterpret_cast<float2*>(o2) = make_float2(acc[mt][nt][2], acc[mt][nt][3]);
        }
    }
}

// ---------------------------------------------------------------------------
// SRU recurrence. One thread per (b, d, dir): 32768 independent scalar scans.
// Chunk-of-4 double-buffered register prefetch (16 loads in flight / thread).
// Layer 0 writes h as fp16 into g_Ah (layer-1 GEMM input).
// Layer 1 writes out1 fp32 + final c into c1.
// ---------------------------------------------------------------------------
__device__ __forceinline__ float sigf(float x) {
    float e = __expf(-x);
    return __fdividef(1.0f, 1.0f + e);
}

__device__ __forceinline__ void rec_load(const float* p, long stride, int ch, float (&u)[4][4]) {
    const float* pn = p + (long)ch * 4 * stride;
#pragma unroll
    for (int j = 0; j < 4; j++) {
        const float* q = pn + (long)j * stride;
        u[j][0] = q[0];        // xt
        u[j][1] = q[512];      // fp
        u[j][2] = q[1024];     // rp
        u[j][3] = q[1536];     // xp
    }
}

template <int LAYER>
__device__ __forceinline__ void rec_comp(float (&u)[4][4], int ch, float& c,
                                         float vfd, float vrd, float bfd, float brd,
                                         __half* hA, float* hO, long hstride) {
#pragma unroll
    for (int j = 0; j < 4; j++) {
        float f  = sigf(u[j][1] + vfd * c + bfd);
        float cn = f * c + (1.0f - f) * u[j][0];
        float r  = sigf(u[j][2] + vrd * c + brd);
        float h  = r * cn + (1.0f - r) * u[j][3] * SCALE_F;
        c = cn;
        long off = (long)(ch * 4 + j) * hstride;
        if (LAYER == 0) hA[off] = __float2half_rn(h);
        else            hO[off] = h;
    }
}

template <int LAYER>
__global__ __launch_bounds__(256) void k_rec(const float* __restrict__ vf,
                                             const float* __restrict__ vr,
                                             const float* __restrict__ bfp,
                                             const float* __restrict__ brp,
                                             float* __restrict__ out1,
                                             float* __restrict__ c1out) {
    const int d   = blockIdx.x * blockDim.x + threadIdx.x;  // 0..511
    const int b   = blockIdx.y;                             // 0..31
    const int dir = blockIdx.z;                             // 0 fwd, 1 bwd

    const float vfd = vf[dir * 512 + d];
    const float vrd = vr[dir * 512 + d];
    const float bfd = bfp[dir * 512 + d];
    const float brd = brp[dir * 512 + d];

    const long stride  = dir ? -4096 : 4096;
    const long hstride = dir ? -1024 : 1024;
    const int  t0      = dir ? 1023 : 0;

    const float* p  = g_U + ((size_t)b * 1024 + t0) * 4096 + dir * 2048 + d;
    __half*      hA = g_Ah + ((size_t)b * 1024 + t0) * 1024 + dir * 512 + d;
    float*       hO = (LAYER == 1)
                      ? out1 + ((size_t)b * 1024 + t0) * 1024 + dir * 512 + d
                      : nullptr;

    float c = 0.0f;
    float uA[4][4], uB[4][4];
    rec_load(p, stride, 0, uA);
    for (int c2 = 0; c2 < 128; c2++) {
        rec_load(p, stride, 2 * c2 + 1, uB);
        rec_comp<LAYER>(uA, 2 * c2, c, vfd, vrd, bfd, brd, hA, hO, hstride);
        if (c2 < 127) rec_load(p, stride, 2 * c2 + 2, uA);
        rec_comp<LAYER>(uB, 2 * c2 + 1, c, vfd, vrd, bfd, brd, hA, hO, hstride);
    }
    if (LAYER == 1) c1out[b * 1024 + dir * 512 + d] = c;
}

// ---------------------------------------------------------------------------
// Launch: cvt(seqs) -> cvt(W0) -> GEMM0 -> rec0 -> cvt(W1) -> GEMM1 -> rec1
// Output layout: d_out = [ c1 (32*1024 fp32) | out1 (32*1024*1024 fp32) ]
// ---------------------------------------------------------------------------
extern "C" void kernel_launch(void* const* d_in, const int* in_sizes, int n_in,
                              void* d_out, int out_size) {
    const float* seqs = (const float*)d_in[0];
    const float* W0   = (const float*)d_in[1];
    const float* vf0  = (const float*)d_in[2];
    const float* vr0  = (const float*)d_in[3];
    const float* bf0  = (const float*)d_in[4];
    const float* br0  = (const float*)d_in[5];
    const float* W1   = (const float*)d_in[6];
    const float* vf1  = (const float*)d_in[7];
    const float* vr1  = (const float*)d_in[8];
    const float* bf1  = (const float*)d_in[9];
    const float* br1  = (const float*)d_in[10];
    // d_in[11] = lengths (unused by the reference)

    float* out  = (float*)d_out;
    float* c1   = out;            // (32, 1024)
    float* out1 = out + 32768;    // (32, 1024, 1024)

    // Layer 0
    k_cvtA<<<16384, 256>>>((const float4*)seqs, 4194304);          // 32768x512 fp32 -> fp16
    k_cvtW<<<2048, 256>>>((const float4*)W0, 524288);              // 512x4096
    k_gemm<512><<<dim3(32, 256), 256>>>();
    k_rec<0><<<dim3(2, 32, 2), 256>>>(vf0, vr0, bf0, br0, nullptr, nullptr);

    // Layer 1
    k_cvtW<<<4096, 256>>>((const float4*)W1, 1048576);             // 1024x4096
    k_gemm<1024><<<dim3(32, 256), 256>>>();
    k_rec<1><<<dim3(2, 32, 2), 256>>>(vf1, vr1, bf1, br1, out1, c1);
}